// round 12
// baseline (speedup 1.0000x reference)
#include <cuda_runtime.h>
#include <cstdint>

#define Bn 2048
#define Tn 512
#define Hn 16
#define Ln 8
#define CWPB 7                          // consumer warps per CTA (2 batches each)
#define BPC (CWPB * 2)                  // 14 batches per CTA
#define NBLK ((Bn + BPC - 1) / BPC)     // 147 CTAs -> 1 per SM, single wave
#define THREADS (CWPB * 2 * 32)         // 448: 7 consumer + 7 producer warps
#define CH 4                            // steps per chunk
#define NCH (Tn / CH)                   // 128 chunks
#define RING 2                          // xproj ring depth (chunks)

typedef unsigned long long ull;
typedef unsigned int u32;

// Ping-pong scratch for inter-layer hidden sequences (64 MB each).
__device__ float g_bufA[(size_t)Bn * Tn * Hn];
__device__ float g_bufB[(size_t)Bn * Tn * Hn];

// ---- packed fp32x2 ops (Blackwell) ----
__device__ __forceinline__ void ffma2(ull& d, ull a, ull b) {
    asm("fma.rn.f32x2 %0, %1, %2, %0;" : "+l"(d) : "l"(a), "l"(b));
}
__device__ __forceinline__ ull fmul2(ull a, ull b) {
    ull r; asm("mul.rn.f32x2 %0, %1, %2;" : "=l"(r) : "l"(a), "l"(b)); return r;
}
__device__ __forceinline__ float2 u2f(ull a) {
    float2 f;
    asm("mov.b64 {%0,%1}, %2;" : "=f"(f.x), "=f"(f.y) : "l"(a));
    return f;
}
__device__ __forceinline__ ull pack2(float x, float y) {
    ull r;
    asm("mov.b64 %0, {%1,%2};" : "=l"(r) : "f"(x), "f"(y));
    return r;
}
// Load 16 contiguous floats as 8 packed f32x2 (4x 128-bit loads).
__device__ __forceinline__ void load8(ull* d, const float* p) {
    const ulonglong2* q = (const ulonglong2*)p;
    ulonglong2 v0 = q[0], v1 = q[1], v2 = q[2], v3 = q[3];
    d[0] = v0.x; d[1] = v0.y; d[2] = v1.x; d[3] = v1.y;
    d[4] = v2.x; d[5] = v2.y; d[6] = v3.x; d[7] = v3.y;
}
__device__ __forceinline__ float tanha(float x) {
    float r; asm("tanh.approx.f32 %0, %1;" : "=f"(r) : "f"(x)); return r;
}
// Predicated GLOBAL store — single @p STG, no BSSY/BSYNC. Global addresses only.
__device__ __forceinline__ void st_pred(float* addr, float v, int pred) {
    asm volatile("{ .reg .pred p; setp.ne.s32 p, %0, 0; @p st.global.f32 [%1], %2; }"
                 :: "r"(pred), "l"(addr), "f"(v));
}
__device__ __forceinline__ void cp16(u32 saddr, const float* g) {
    asm volatile("cp.async.cg.shared.global [%0], [%1], 16;" :: "r"(saddr), "l"(g));
}
__device__ __forceinline__ void cp_commit() { asm volatile("cp.async.commit_group;"); }
__device__ __forceinline__ void cp_wait1()  { asm volatile("cp.async.wait_group 1;"); }

// Acquire/release counters (CTA scope, shared memory).
__device__ __forceinline__ int ld_acq(const int* p) {
    int v;
    asm volatile("ld.acquire.cta.shared.b32 %0, [%1];"
                 : "=r"(v) : "r"((u32)__cvta_generic_to_shared(p)));
    return v;
}
__device__ __forceinline__ void st_rel(int* p, int v) {
    asm volatile("st.release.cta.shared.b32 [%0], %1;"
                 :: "r"((u32)__cvta_generic_to_shared(p)), "r"(v));
}
__device__ __forceinline__ void backoff() { __nanosleep(64); }

// Warp-specialized LSTM layer, per-pair decoupled via acquire/release counters.
//  Warps 0..6   (consumers): h-proj + activations, 2 batches each.
//  Warps 7..13  (producers): x-proj GEMM, up to RING-1 chunks ahead of own consumer.
template <bool WRITE_ALL>
__global__ void __launch_bounds__(THREADS, 1)
lstm_layer(const float* __restrict__ in, float* __restrict__ out,
           const float* __restrict__ Wih, const float* __restrict__ Whh,
           const float* __restrict__ bih, const float* __restrict__ bhh)
{
    __shared__ __align__(16) float4 xsp[RING][CWPB][2][CH][Hn];  // xproj ring
    __shared__ __align__(16) float  xraw[2][CWPB][2][CH][Hn];    // staged raw x
    __shared__ __align__(16) float  sh[CWPB][2][2][Hn];          // h exchange
    __shared__ __align__(16) int    prod_cnt[CWPB];              // chunks published
    __shared__ __align__(16) int    cons_cnt[CWPB];              // chunks consumed

    const int wid  = threadIdx.x >> 5;
    const int lane = threadIdx.x & 31;
    const int half = lane >> 4;
    const int j    = lane & 15;
    const bool producer = wid >= CWPB;
    const int w = producer ? wid - CWPB : wid;

    int bb = blockIdx.x * BPC + w * 2 + half;       // this lane's batch
    const int valid = bb < Bn;
    if (!valid) bb = 0;                             // clamp: reads safe, stores predicated

    // common init (uniform path), then one block barrier
    if (threadIdx.x < CWPB) { prod_cnt[threadIdx.x] = 0; cons_cnt[threadIdx.x] = 0; }
    if (!producer) sh[w][0][half][j] = 0.0f;
    __syncthreads();

    if (!producer) {
        // ================= CONSUMER =================
        ull wh[4][8];
        const ull halfpack = pack2(0.5f, 0.5f);
#pragma unroll
        for (int q = 0; q < 4; q++) {
            load8(wh[q], Whh + (q * Hn + j) * Hn);
            if (q != 2) {
#pragma unroll
                for (int i = 0; i < 8; i++) wh[q][i] = fmul2(wh[q][i], halfpack);
            }
        }
        float c = 0.0f;
        float* orow = out + (size_t)bb * Tn * Hn;

        for (int ch = 0; ch < NCH; ch++) {
            const int buf = ch & (RING - 1);
            // wait for producer to publish chunk ch (usually already done)
            while (ld_acq(&prod_cnt[w]) < ch + 1) { backoff(); }

#pragma unroll
            for (int s = 0; s < CH; s++) {
                const int t = ch * CH + s;

                ull hp[8];
                load8(hp, &sh[w][s & 1][half][0]);       // t&1 == s&1 (CH even)
                const float4 xp = xsp[buf][w][half][s][j];

                ull a0 = pack2(xp.x, 0.0f), a1 = pack2(xp.y, 0.0f);
                ull a2 = pack2(xp.z, 0.0f), a3 = pack2(xp.w, 0.0f);
#pragma unroll
                for (int i = 0; i < 8; i++) {
                    ffma2(a0, wh[0][i], hp[i]); ffma2(a1, wh[1][i], hp[i]);
                    ffma2(a2, wh[2][i], hp[i]); ffma2(a3, wh[3][i], hp[i]);
                }
                float2 F0 = u2f(a0), F1 = u2f(a1), F2 = u2f(a2), F3 = u2f(a3);
                const float vi = F0.x + F0.y;   // pre-halved
                const float vf = F1.x + F1.y;   // pre-halved
                const float vg = F2.x + F2.y;
                const float vo = F3.x + F3.y;   // pre-halved

                const float si = fmaf(0.5f, tanha(vi), 0.5f);
                const float sf = fmaf(0.5f, tanha(vf), 0.5f);
                const float tg = tanha(vg);
                const float so = fmaf(0.5f, tanha(vo), 0.5f);

                c = fmaf(sf, c, si * tg);
                const float h = so * tanha(c);

                sh[w][(s + 1) & 1][half][j] = h;
                __syncwarp();
                if (WRITE_ALL || t == Tn - 1)
                    st_pred(orow + t * Hn + j, h, valid);
            }
            // free the ring slot for the producer
            if (lane == 0) st_rel(&cons_cnt[w], ch + 1);
        }
    } else {
        // ================= PRODUCER =================
        ull wx[4][8], bias[4];
        const ull halfpack = pack2(0.5f, 0.5f);
#pragma unroll
        for (int q = 0; q < 4; q++) {
            const int row = q * Hn + j;
            load8(wx[q], Wih + row * Hn);
            float bbv = bih[row] + bhh[row];
            if (q != 2) {
                bbv *= 0.5f;
#pragma unroll
                for (int i = 0; i < 8; i++) wx[q][i] = fmul2(wx[q][i], halfpack);
            }
            bias[q] = pack2(bbv, 0.0f);
        }

        // x staging: lane copies 16B segment (half = batch, seg = lane&15)
        int b0c = blockIdx.x * BPC + w * 2;     int b1c = b0c + 1;
        if (b0c >= Bn) b0c = 0;
        if (b1c >= Bn) b1c = 0;
        const float* xrow_my = in + (size_t)((lane < 16) ? b0c : b1c) * Tn * Hn;
        const int seg = j;
        const u32 base0 = (u32)__cvta_generic_to_shared(&xraw[0][w][0][0][0]);
        const u32 base1 = (u32)__cvta_generic_to_shared(&xraw[1][w][0][0][0]);
        const u32 dst_off = (u32)half * (CH * Hn * 4) + (u32)seg * 16;

        // prologue: stage x chunks 0 and 1; compute xproj chunk 0; publish
        cp16(base0 + dst_off, xrow_my + 0 * (CH * Hn) + seg * 4);
        cp_commit();
        cp16(base1 + dst_off, xrow_my + 1 * (CH * Hn) + seg * 4);
        cp_commit();
        cp_wait1();       // chunk 0 resident
        __syncwarp();
#pragma unroll
        for (int s = 0; s < CH; s++) {
            ull xv[8];
            load8(xv, &xraw[0][w][half][s][0]);
            ull a0 = bias[0], a1 = bias[1], a2 = bias[2], a3 = bias[3];
#pragma unroll
            for (int i = 0; i < 8; i++) {
                ffma2(a0, wx[0][i], xv[i]); ffma2(a1, wx[1][i], xv[i]);
                ffma2(a2, wx[2][i], xv[i]); ffma2(a3, wx[3][i], xv[i]);
            }
            float2 F0 = u2f(a0), F1 = u2f(a1), F2 = u2f(a2), F3 = u2f(a3);
            xsp[0][w][half][s][j] = make_float4(F0.x + F0.y, F1.x + F1.y,
                                                F2.x + F2.y, F3.x + F3.y);
        }
        __syncwarp();
        if (lane == 0) st_rel(&prod_cnt[w], 1);

        for (int ch = 0; ch < NCH; ch++) {
            // prefetch x chunk ch+2 into xraw[ch&1] (slot last read a full chunk ago)
            const int nc = (ch + 2 < NCH) ? ch + 2 : NCH - 1;
            cp16(((ch & 1) ? base1 : base0) + dst_off,
                 xrow_my + nc * (CH * Hn) + seg * 4);
            cp_commit();

            const int k = ch + 1;         // chunk to compute & publish
            if (k < NCH) {
                cp_wait1();               // x chunk k resident in xraw[k&1]
                __syncwarp();
                // ring flow control: slot k&1 free once consumer finished chunk k-RING+1
                while (ld_acq(&cons_cnt[w]) < k - (RING - 1)) { backoff(); }
                const int bi = k & 1;
                const int rb = k & (RING - 1);
#pragma unroll
                for (int s = 0; s < CH; s++) {
                    ull xv[8];
                    load8(xv, &xraw[bi][w][half][s][0]);
                    ull a0 = bias[0], a1 = bias[1], a2 = bias[2], a3 = bias[3];
#pragma unroll
                    for (int i = 0; i < 8; i++) {
                        ffma2(a0, wx[0][i], xv[i]); ffma2(a1, wx[1][i], xv[i]);
                        ffma2(a2, wx[2][i], xv[i]); ffma2(a3, wx[3][i], xv[i]);
                    }
                    float2 F0 = u2f(a0), F1 = u2f(a1), F2 = u2f(a2), F3 = u2f(a3);
                    xsp[rb][w][half][s][j] = make_float4(F0.x + F0.y, F1.x + F1.y,
                                                         F2.x + F2.y, F3.x + F3.y);
                }
                __syncwarp();
                if (lane == 0) st_rel(&prod_cnt[w], k + 1);
            }
        }
    }
}

// Readout: position = last @ Wp^T + bp ; orientation = tanh(last @ Wo^T + bo)
__global__ void head_kernel(const float* __restrict__ hbuf,
                            const float* __restrict__ Wp, const float* __restrict__ bp,
                            const float* __restrict__ Wo, const float* __restrict__ bo,
                            float* __restrict__ out)
{
    int b = blockIdx.x * blockDim.x + threadIdx.x;
    if (b >= Bn) return;
    const float* h = hbuf + (size_t)b * Tn * Hn + (size_t)(Tn - 1) * Hn;
    float hv[16];
#pragma unroll
    for (int i = 0; i < 16; i++) hv[i] = h[i];

#pragma unroll
    for (int r = 0; r < 3; r++) {
        float s = bp[r];
#pragma unroll
        for (int k = 0; k < 16; k++) s += hv[k] * Wp[r * 16 + k];
        out[b * 6 + r] = s;
    }
#pragma unroll
    for (int r = 0; r < 3; r++) {
        float s = bo[r];
#pragma unroll
        for (int k = 0; k < 16; k++) s += hv[k] * Wo[r * 16 + k];
        out[b * 6 + 3 + r] = tanha(s);
    }
}

extern "C" void kernel_launch(void* const* d_in, const int* in_sizes, int n_in,
                              void* d_out, int out_size)
{
    const float* x   = (const float*)d_in[0];
    const float* Wih = (const float*)d_in[1];
    const float* Whh = (const float*)d_in[2];
    const float* bih = (const float*)d_in[3];
    const float* bhh = (const float*)d_in[4];
    const float* Wp  = (const float*)d_in[5];
    const float* bp  = (const float*)d_in[6];
    const float* Wo  = (const float*)d_in[7];
    const float* bo  = (const float*)d_in[8];
    float* out = (float*)d_out;

    float *bufA, *bufB;
    cudaGetSymbolAddress((void**)&bufA, g_bufA);
    cudaGetSymbolAddress((void**)&bufB, g_bufB);

    const float* cur = x;
    for (int l = 0; l < Ln; l++) {
        float* o = (l & 1) ? bufB : bufA;
        if (l != Ln - 1)
            lstm_layer<true><<<NBLK, THREADS>>>(cur, o,
                                                Wih + (size_t)l * 64 * Hn,
                                                Whh + (size_t)l * 64 * Hn,
                                                bih + (size_t)l * 64,
                                                bhh + (size_t)l * 64);
        else
            lstm_layer<false><<<NBLK, THREADS>>>(cur, o,
                                                 Wih + (size_t)l * 64 * Hn,
                                                 Whh + (size_t)l * 64 * Hn,
                                                 bih + (size_t)l * 64,
                                                 bhh + (size_t)l * 64);
        cur = o;
    }
    head_kernel<<<(Bn + 255) / 256, 256>>>(cur, Wp, bp, Wo, bo, out);
}

// round 13
// speedup vs baseline: 1.0964x; 1.0964x over previous
#include <cuda_runtime.h>
#include <cstdint>

#define Bn 2048
#define Tn 512
#define Hn 16
#define Ln 8
#define WPB 7                          // warps per CTA
#define BPC (WPB * 2)                  // 14 batches per CTA
#define NBLK ((Bn + BPC - 1) / BPC)    // 147 CTAs -> 1 per SM
#define CHUNK 16
#define NCHUNK (Tn / CHUNK)

typedef unsigned long long ull;
typedef unsigned int u32;

// Ping-pong scratch for inter-layer hidden sequences (64 MB each).
__device__ float g_bufA[(size_t)Bn * Tn * Hn];
__device__ float g_bufB[(size_t)Bn * Tn * Hn];

// ---- packed fp32x2 ops (Blackwell) ----
__device__ __forceinline__ void ffma2(ull& d, ull a, ull b) {
    asm("fma.rn.f32x2 %0, %1, %2, %0;" : "+l"(d) : "l"(a), "l"(b));
}
__device__ __forceinline__ ull fmul2(ull a, ull b) {
    ull r; asm("mul.rn.f32x2 %0, %1, %2;" : "=l"(r) : "l"(a), "l"(b)); return r;
}
__device__ __forceinline__ float2 u2f(ull a) {
    float2 f;
    asm("mov.b64 {%0,%1}, %2;" : "=f"(f.x), "=f"(f.y) : "l"(a));
    return f;
}
__device__ __forceinline__ ull pack2(float x, float y) {
    ull r;
    asm("mov.b64 %0, {%1,%2};" : "=l"(r) : "f"(x), "f"(y));
    return r;
}
// Load 16 contiguous floats as 8 packed f32x2 (4x 128-bit loads).
__device__ __forceinline__ void load8(ull* d, const float* p) {
    const ulonglong2* q = (const ulonglong2*)p;
    ulonglong2 v0 = q[0], v1 = q[1], v2 = q[2], v3 = q[3];
    d[0] = v0.x; d[1] = v0.y; d[2] = v1.x; d[3] = v1.y;
    d[4] = v2.x; d[5] = v2.y; d[6] = v3.x; d[7] = v3.y;
}
__device__ __forceinline__ float tanha(float x) {
    float r; asm("tanh.approx.f32 %0, %1;" : "=f"(r) : "f"(x)); return r;
}
__device__ __forceinline__ void cp16(u32 saddr, const float* g) {
    asm volatile("cp.async.cg.shared.global [%0], [%1], 16;" :: "r"(saddr), "l"(g));
}
__device__ __forceinline__ void cp_commit() { asm volatile("cp.async.commit_group;"); }
__device__ __forceinline__ void cp_wait0()  { asm volatile("cp.async.wait_group 0;"); }

// One LSTM layer. Warp = TWO batch elements (lanes 0-15 / 16-31).
// Lane (half, j) owns hidden unit j of its batch: gate rows j, 16+j, 32+j, 48+j.
// Weights in registers (f32x2; sigmoid rows pre-scaled by 0.5).
// h via smem broadcast. x staged via cp.async chunks; x-projection for step s+1
// software-pipelined into step s's activation window. Warps 4..6 start with a
// ~half-step phase skew so the two warps per SMSP interleave chain vs FMA phases.
template <bool WRITE_ALL>
__global__ void __launch_bounds__(224, 1)
lstm_layer(const float* __restrict__ in, float* __restrict__ out,
           const float* __restrict__ Wih, const float* __restrict__ Whh,
           const float* __restrict__ bih, const float* __restrict__ bhh)
{
    __shared__ __align__(16) float sh[WPB][2][2][Hn];            // [warp][parity][half][j]
    __shared__ __align__(16) float xs[WPB][2][2][CHUNK][Hn];     // [warp][buf][half][step][j]

    const int warp = threadIdx.x >> 5;
    const int lane = threadIdx.x & 31;
    const int half = lane >> 4;
    const int j    = lane & 15;
    const int b    = blockIdx.x * BPC + warp * 2 + half;
    if (b >= Bn) return;   // warp-uniform exit

    // ---- weights -> registers; sigmoid-gate rows scaled by 0.5 ----
    ull wx[4][8], wh[4][8], bias[4];
    const ull halfpack = pack2(0.5f, 0.5f);
#pragma unroll
    for (int q = 0; q < 4; q++) {
        const int row = q * Hn + j;          // q: 0=i 1=f 2=g 3=o
        load8(wx[q], Wih + row * Hn);
        load8(wh[q], Whh + row * Hn);
        float bb = bih[row] + bhh[row];
        if (q != 2) {
            bb *= 0.5f;
#pragma unroll
            for (int i = 0; i < 8; i++) {
                wx[q][i] = fmul2(wx[q][i], halfpack);
                wh[q][i] = fmul2(wh[q][i], halfpack);
            }
        }
        bias[q] = pack2(bb, 0.0f);
    }

    sh[warp][0][half][j] = 0.0f;
    float c = 0.0f;

    const float* xptr = in + (size_t)b * Tn * Hn;
    float*       orow = out + (size_t)b * Tn * Hn;

    // prefetch chunk 0 (per half: 1 KB contiguous; 4 cp16/lane)
    {
        u32 s0 = (u32)__cvta_generic_to_shared(&xs[warp][0][half][0][0]);
#pragma unroll
        for (int k = 0; k < 4; k++)
            cp16(s0 + (k * 16 + j) * 16, xptr + (k * 16 + j) * 4);
        cp_commit();
    }
    __syncwarp();

    // ---- phase skew: second warp on each SMSP (wid 4..6) delays ~224 cyc ----
    {
        const int skew = (warp >= 4) ? 56 : 0;
        float dd = (float)lane;
#pragma unroll 1
        for (int k = 0; k < skew; k++)
            asm volatile("add.f32 %0, %0, 0f3F800000;" : "+f"(dd));  // dependent chain, lat 4 each
    }

    ull ax0, ax1, ax2, ax3;   // pipelined x-projection accumulators

    for (int ch = 0; ch < NCHUNK; ch++) {
        const int cur = ch & 1;
        cp_wait0();
        __syncwarp();

        // prefetch chunk ch+1 (clamped refetch at tail — harmless)
        {
            const int nch = (ch + 1 < NCHUNK) ? ch + 1 : ch;
            const float* g = xptr + nch * (CHUNK * Hn);
            u32 s0 = (u32)__cvta_generic_to_shared(&xs[warp][cur ^ 1][half][0][0]);
#pragma unroll
            for (int k = 0; k < 4; k++)
                cp16(s0 + (k * 16 + j) * 16, g + (k * 16 + j) * 4);
            cp_commit();
        }

        // prologue: x-projection for s = 0 of this chunk
        {
            ull xv[8];
            load8(xv, &xs[warp][cur][half][0][0]);
            ax0 = bias[0]; ax1 = bias[1]; ax2 = bias[2]; ax3 = bias[3];
#pragma unroll
            for (int i = 0; i < 8; i++) {
                ffma2(ax0, wx[0][i], xv[i]); ffma2(ax1, wx[1][i], xv[i]);
                ffma2(ax2, wx[2][i], xv[i]); ffma2(ax3, wx[3][i], xv[i]);
            }
        }

#pragma unroll 4
        for (int s = 0; s < CHUNK; s++) {
            const int t = ch * CHUNK + s;

            // --- critical: h-projection onto pipelined x-projection ---
            ull hp[8];
            load8(hp, &sh[warp][s & 1][half][0]);
            ull a0 = ax0, a1 = ax1, a2 = ax2, a3 = ax3;
#pragma unroll
            for (int i = 0; i < 8; i++) {
                ffma2(a0, wh[0][i], hp[i]); ffma2(a1, wh[1][i], hp[i]);
                ffma2(a2, wh[2][i], hp[i]); ffma2(a3, wh[3][i], hp[i]);
            }

            // --- off-chain: x-projection for step s+1 (fills MUFU shadow) ---
            {
                ull xv[8];
                load8(xv, &xs[warp][cur][half][(s + 1) & 15][0]);  // s=15: dummy, redone
                ax0 = bias[0]; ax1 = bias[1]; ax2 = bias[2]; ax3 = bias[3];
#pragma unroll
                for (int i = 0; i < 8; i++) {
                    ffma2(ax0, wx[0][i], xv[i]); ffma2(ax1, wx[1][i], xv[i]);
                    ffma2(ax2, wx[2][i], xv[i]); ffma2(ax3, wx[3][i], xv[i]);
                }
            }

            // --- activations ---
            float2 F0 = u2f(a0), F1 = u2f(a1), F2 = u2f(a2), F3 = u2f(a3);
            const float vi = F0.x + F0.y;   // pre-halved
            const float vf = F1.x + F1.y;   // pre-halved
            const float vg = F2.x + F2.y;
            const float vo = F3.x + F3.y;   // pre-halved

            const float si = fmaf(0.5f, tanha(vi), 0.5f);
            const float sf = fmaf(0.5f, tanha(vf), 0.5f);
            const float tg = tanha(vg);
            const float so = fmaf(0.5f, tanha(vo), 0.5f);

            c = fmaf(sf, c, si * tg);
            const float h = so * tanha(c);

            sh[warp][(s + 1) & 1][half][j] = h;
            __syncwarp();
            if (WRITE_ALL || t == Tn - 1)           // compile-time predicate
                orow[t * Hn + j] = h;
        }
    }
}

// Readout: position = last @ Wp^T + bp ; orientation = tanh(last @ Wo^T + bo)
__global__ void head_kernel(const float* __restrict__ hbuf,
                            const float* __restrict__ Wp, const float* __restrict__ bp,
                            const float* __restrict__ Wo, const float* __restrict__ bo,
                            float* __restrict__ out)
{
    int b = blockIdx.x * blockDim.x + threadIdx.x;
    if (b >= Bn) return;
    const float* h = hbuf + (size_t)b * Tn * Hn + (size_t)(Tn - 1) * Hn;
    float hv[16];
#pragma unroll
    for (int i = 0; i < 16; i++) hv[i] = h[i];

#pragma unroll
    for (int r = 0; r < 3; r++) {
        float s = bp[r];
#pragma unroll
        for (int k = 0; k < 16; k++) s += hv[k] * Wp[r * 16 + k];
        out[b * 6 + r] = s;
    }
#pragma unroll
    for (int r = 0; r < 3; r++) {
        float s = bo[r];
#pragma unroll
        for (int k = 0; k < 16; k++) s += hv[k] * Wo[r * 16 + k];
        out[b * 6 + 3 + r] = tanha(s);
    }
}

extern "C" void kernel_launch(void* const* d_in, const int* in_sizes, int n_in,
                              void* d_out, int out_size)
{
    const float* x   = (const float*)d_in[0];
    const float* Wih = (const float*)d_in[1];
    const float* Whh = (const float*)d_in[2];
    const float* bih = (const float*)d_in[3];
    const float* bhh = (const float*)d_in[4];
    const float* Wp  = (const float*)d_in[5];
    const float* bp  = (const float*)d_in[6];
    const float* Wo  = (const float*)d_in[7];
    const float* bo  = (const float*)d_in[8];
    float* out = (float*)d_out;

    float *bufA, *bufB;
    cudaGetSymbolAddress((void**)&bufA, g_bufA);
    cudaGetSymbolAddress((void**)&bufB, g_bufB);

    const float* cur = x;
    for (int l = 0; l < Ln; l++) {
        float* o = (l & 1) ? bufB : bufA;
        if (l != Ln - 1)
            lstm_layer<true><<<NBLK, 224>>>(cur, o,
                                            Wih + (size_t)l * 64 * Hn,
                                            Whh + (size_t)l * 64 * Hn,
                                            bih + (size_t)l * 64,
                                            bhh + (size_t)l * 64);
        else
            lstm_layer<false><<<NBLK, 224>>>(cur, o,
                                             Wih + (size_t)l * 64 * Hn,
                                             Whh + (size_t)l * 64 * Hn,
                                             bih + (size_t)l * 64,
                                             bhh + (size_t)l * 64);
        cur = o;
    }
    head_kernel<<<(Bn + 255) / 256, 256>>>(cur, Wp, bp, Wo, bo, out);
}

// round 14
// speedup vs baseline: 1.1108x; 1.0132x over previous
#include <cuda_runtime.h>
#include <cstdint>

#define Bn 2048
#define Tn 512
#define Hn 16
#define Ln 8
#define WPB 7                          // warps per CTA
#define BPC (WPB * 2)                  // 14 batches per CTA
#define NBLK ((Bn + BPC - 1) / BPC)    // 147 CTAs -> 1 per SM
#define CHUNK 16
#define NCHUNK (Tn / CHUNK)

typedef unsigned long long ull;
typedef unsigned int u32;

// Ping-pong scratch for inter-layer hidden sequences (64 MB each).
__device__ float g_bufA[(size_t)Bn * Tn * Hn];
__device__ float g_bufB[(size_t)Bn * Tn * Hn];

// ---- packed fp32x2 ops (Blackwell) ----
__device__ __forceinline__ void ffma2(ull& d, ull a, ull b) {
    asm("fma.rn.f32x2 %0, %1, %2, %0;" : "+l"(d) : "l"(a), "l"(b));
}
__device__ __forceinline__ ull fmul2(ull a, ull b) {
    ull r; asm("mul.rn.f32x2 %0, %1, %2;" : "=l"(r) : "l"(a), "l"(b)); return r;
}
__device__ __forceinline__ float2 u2f(ull a) {
    float2 f;
    asm("mov.b64 {%0,%1}, %2;" : "=f"(f.x), "=f"(f.y) : "l"(a));
    return f;
}
__device__ __forceinline__ ull pack2(float x, float y) {
    ull r;
    asm("mov.b64 %0, {%1,%2};" : "=l"(r) : "f"(x), "f"(y));
    return r;
}
// Load 16 contiguous floats as 8 packed f32x2 (4x 128-bit loads).
__device__ __forceinline__ void load8(ull* d, const float* p) {
    const ulonglong2* q = (const ulonglong2*)p;
    ulonglong2 v0 = q[0], v1 = q[1], v2 = q[2], v3 = q[3];
    d[0] = v0.x; d[1] = v0.y; d[2] = v1.x; d[3] = v1.y;
    d[4] = v2.x; d[5] = v2.y; d[6] = v3.x; d[7] = v3.y;
}
__device__ __forceinline__ float tanha(float x) {
    float r; asm("tanh.approx.f32 %0, %1;" : "=f"(r) : "f"(x)); return r;
}
__device__ __forceinline__ void cp16(u32 saddr, const float* g) {
    asm volatile("cp.async.cg.shared.global [%0], [%1], 16;" :: "r"(saddr), "l"(g));
}
__device__ __forceinline__ void cp_commit() { asm volatile("cp.async.commit_group;"); }
__device__ __forceinline__ void cp_wait0()  { asm volatile("cp.async.wait_group 0;"); }

// One LSTM layer. Warp = TWO batch elements (lanes 0-15 / 16-31).
// Lane (half, j) owns hidden unit j of its batch: gate rows j, 16+j, 32+j, 48+j.
// Weights in registers (f32x2; sigmoid rows pre-scaled by 0.5). h via smem.
// x staged via cp.async chunks; the x-projection for step s+1 is pipelined into
// step s. The chunk-boundary wait happens at s=12 (off the recurrent path), and
// s=15 computes the NEXT chunk's xproj(0) directly from the next buffer.
template <bool WRITE_ALL>
__global__ void __launch_bounds__(224, 1)
lstm_layer(const float* __restrict__ in, float* __restrict__ out,
           const float* __restrict__ Wih, const float* __restrict__ Whh,
           const float* __restrict__ bih, const float* __restrict__ bhh)
{
    __shared__ __align__(16) float sh[WPB][2][2][Hn];            // [warp][parity][half][j]
    __shared__ __align__(16) float xs[WPB][2][2][CHUNK][Hn];     // [warp][buf][half][step][j]

    const int warp = threadIdx.x >> 5;
    const int lane = threadIdx.x & 31;
    const int half = lane >> 4;
    const int j    = lane & 15;
    const int b    = blockIdx.x * BPC + warp * 2 + half;
    if (b >= Bn) return;   // warp-uniform exit

    // ---- weights -> registers; sigmoid-gate rows scaled by 0.5 ----
    ull wx[4][8], wh[4][8], bias[4];
    const ull halfpack = pack2(0.5f, 0.5f);
#pragma unroll
    for (int q = 0; q < 4; q++) {
        const int row = q * Hn + j;          // q: 0=i 1=f 2=g 3=o
        load8(wx[q], Wih + row * Hn);
        load8(wh[q], Whh + row * Hn);
        float bb = bih[row] + bhh[row];
        if (q != 2) {
            bb *= 0.5f;
#pragma unroll
            for (int i = 0; i < 8; i++) {
                wx[q][i] = fmul2(wx[q][i], halfpack);
                wh[q][i] = fmul2(wh[q][i], halfpack);
            }
        }
        bias[q] = pack2(bb, 0.0f);
    }

    sh[warp][0][half][j] = 0.0f;
    float c = 0.0f;

    const float* xptr = in + (size_t)b * Tn * Hn;
    float*       orow = out + (size_t)b * Tn * Hn;

    // prefetch chunk 0 into buf 0 and wait
    {
        u32 s0 = (u32)__cvta_generic_to_shared(&xs[warp][0][half][0][0]);
#pragma unroll
        for (int k = 0; k < 4; k++)
            cp16(s0 + (k * 16 + j) * 16, xptr + (k * 16 + j) * 4);
        cp_commit();
        cp_wait0();
    }
    __syncwarp();

    // initial x-projection: chunk 0, step 0
    ull ax0, ax1, ax2, ax3;
    {
        ull xv[8];
        load8(xv, &xs[warp][0][half][0][0]);
        ax0 = bias[0]; ax1 = bias[1]; ax2 = bias[2]; ax3 = bias[3];
#pragma unroll
        for (int i = 0; i < 8; i++) {
            ffma2(ax0, wx[0][i], xv[i]); ffma2(ax1, wx[1][i], xv[i]);
            ffma2(ax2, wx[2][i], xv[i]); ffma2(ax3, wx[3][i], xv[i]);
        }
    }

    // One LSTM step: h-proj on pipelined ax, refill ax from xsrc, activations.
    auto STEP = [&](int s, int t, const float* xsrc) {
        ull hp[8];
        load8(hp, &sh[warp][s & 1][half][0]);
        ull a0 = ax0, a1 = ax1, a2 = ax2, a3 = ax3;
#pragma unroll
        for (int i = 0; i < 8; i++) {
            ffma2(a0, wh[0][i], hp[i]); ffma2(a1, wh[1][i], hp[i]);
            ffma2(a2, wh[2][i], hp[i]); ffma2(a3, wh[3][i], hp[i]);
        }
        // off-chain: next x-projection (fills the activation-latency window)
        {
            ull xv[8];
            load8(xv, xsrc);
            ax0 = bias[0]; ax1 = bias[1]; ax2 = bias[2]; ax3 = bias[3];
#pragma unroll
            for (int i = 0; i < 8; i++) {
                ffma2(ax0, wx[0][i], xv[i]); ffma2(ax1, wx[1][i], xv[i]);
                ffma2(ax2, wx[2][i], xv[i]); ffma2(ax3, wx[3][i], xv[i]);
            }
        }
        float2 F0 = u2f(a0), F1 = u2f(a1), F2 = u2f(a2), F3 = u2f(a3);
        const float vi = F0.x + F0.y;   // pre-halved
        const float vf = F1.x + F1.y;   // pre-halved
        const float vg = F2.x + F2.y;
        const float vo = F3.x + F3.y;   // pre-halved

        const float si = fmaf(0.5f, tanha(vi), 0.5f);
        const float sf = fmaf(0.5f, tanha(vf), 0.5f);
        const float tg = tanha(vg);
        const float so = fmaf(0.5f, tanha(vo), 0.5f);

        c = fmaf(sf, c, si * tg);
        const float h = so * tanha(c);

        sh[warp][(s + 1) & 1][half][j] = h;
        __syncwarp();
        if (WRITE_ALL || t == Tn - 1)
            orow[t * Hn + j] = h;
    };

    for (int ch = 0; ch < NCHUNK; ch++) {
        const int cur = ch & 1;
        const int t0  = ch * CHUNK;

        // issue prefetch of chunk ch+1 into buf cur^1 (clamped refetch at tail)
        {
            const int nch = (ch + 1 < NCHUNK) ? ch + 1 : ch;
            const float* g = xptr + nch * (CHUNK * Hn);
            u32 s0 = (u32)__cvta_generic_to_shared(&xs[warp][cur ^ 1][half][0][0]);
#pragma unroll
            for (int k = 0; k < 4; k++)
                cp16(s0 + (k * 16 + j) * 16, g + (k * 16 + j) * 4);
            cp_commit();
        }

#pragma unroll 4
        for (int s = 0; s < 12; s++)
            STEP(s, t0 + s, &xs[warp][cur][half][s + 1][0]);

        cp_wait0();          // chunk ch+1 resident (issued 12 steps ago)
        __syncwarp();

        STEP(12, t0 + 12, &xs[warp][cur][half][13][0]);
        STEP(13, t0 + 13, &xs[warp][cur][half][14][0]);
        STEP(14, t0 + 14, &xs[warp][cur][half][15][0]);
        // s=15: refill ax from the NEXT chunk's slot 0 (already resident)
        STEP(15, t0 + 15, &xs[warp][cur ^ 1][half][0][0]);
    }
}

// Readout: position = last @ Wp^T + bp ; orientation = tanh(last @ Wo^T + bo)
__global__ void head_kernel(const float* __restrict__ hbuf,
                            const float* __restrict__ Wp, const float* __restrict__ bp,
                            const float* __restrict__ Wo, const float* __restrict__ bo,
                            float* __restrict__ out)
{
    int b = blockIdx.x * blockDim.x + threadIdx.x;
    if (b >= Bn) return;
    const float* h = hbuf + (size_t)b * Tn * Hn + (size_t)(Tn - 1) * Hn;
    float hv[16];
#pragma unroll
    for (int i = 0; i < 16; i++) hv[i] = h[i];

#pragma unroll
    for (int r = 0; r < 3; r++) {
        float s = bp[r];
#pragma unroll
        for (int k = 0; k < 16; k++) s += hv[k] * Wp[r * 16 + k];
        out[b * 6 + r] = s;
    }
#pragma unroll
    for (int r = 0; r < 3; r++) {
        float s = bo[r];
#pragma unroll
        for (int k = 0; k < 16; k++) s += hv[k] * Wo[r * 16 + k];
        out[b * 6 + 3 + r] = tanha(s);
    }
}

extern "C" void kernel_launch(void* const* d_in, const int* in_sizes, int n_in,
                              void* d_out, int out_size)
{
    const float* x   = (const float*)d_in[0];
    const float* Wih = (const float*)d_in[1];
    const float* Whh = (const float*)d_in[2];
    const float* bih = (const float*)d_in[3];
    const float* bhh = (const float*)d_in[4];
    const float* Wp  = (const float*)d_in[5];
    const float* bp  = (const float*)d_in[6];
    const float* Wo  = (const float*)d_in[7];
    const float* bo  = (const float*)d_in[8];
    float* out = (float*)d_out;

    float *bufA, *bufB;
    cudaGetSymbolAddress((void**)&bufA, g_bufA);
    cudaGetSymbolAddress((void**)&bufB, g_bufB);

    const float* cur = x;
    for (int l = 0; l < Ln; l++) {
        float* o = (l & 1) ? bufB : bufA;
        if (l != Ln - 1)
            lstm_layer<true><<<NBLK, 224>>>(cur, o,
                                            Wih + (size_t)l * 64 * Hn,
                                            Whh + (size_t)l * 64 * Hn,
                                            bih + (size_t)l * 64,
                                            bhh + (size_t)l * 64);
        else
            lstm_layer<false><<<NBLK, 224>>>(cur, o,
                                             Wih + (size_t)l * 64 * Hn,
                                             Whh + (size_t)l * 64 * Hn,
                                             bih + (size_t)l * 64,
                                             bhh + (size_t)l * 64);
        cur = o;
    }
    head_kernel<<<(Bn + 255) / 256, 256>>>(cur, Wp, bp, Wo, bo, out);
}

// round 15
// speedup vs baseline: 1.1398x; 1.0261x over previous
#include <cuda_runtime.h>
#include <cstdint>

#define Bn 2048
#define Tn 512
#define Hn 16
#define Ln 8
#define WPB 7                          // warps per CTA
#define BPC (WPB * 2)                  // 14 batches per CTA
#define NBLK ((Bn + BPC - 1) / BPC)    // 147 CTAs -> 1 per SM
#define CHUNK 16
#define NCHUNK (Tn / CHUNK)

typedef unsigned long long ull;
typedef unsigned int u32;

// Ping-pong scratch for inter-layer hidden sequences (64 MB each).
__device__ float g_bufA[(size_t)Bn * Tn * Hn];
__device__ float g_bufB[(size_t)Bn * Tn * Hn];

// ---- packed fp32x2 ops (Blackwell) ----
__device__ __forceinline__ void ffma2(ull& d, ull a, ull b) {
    asm("fma.rn.f32x2 %0, %1, %2, %0;" : "+l"(d) : "l"(a), "l"(b));
}
__device__ __forceinline__ ull fmul2(ull a, ull b) {
    ull r; asm("mul.rn.f32x2 %0, %1, %2;" : "=l"(r) : "l"(a), "l"(b)); return r;
}
__device__ __forceinline__ float2 u2f(ull a) {
    float2 f;
    asm("mov.b64 {%0,%1}, %2;" : "=f"(f.x), "=f"(f.y) : "l"(a));
    return f;
}
__device__ __forceinline__ ull pack2(float x, float y) {
    ull r;
    asm("mov.b64 %0, {%1,%2};" : "=l"(r) : "f"(x), "f"(y));
    return r;
}
// Load 16 contiguous floats as 8 packed f32x2 (4x 128-bit loads).
__device__ __forceinline__ void load8(ull* d, const float* p) {
    const ulonglong2* q = (const ulonglong2*)p;
    ulonglong2 v0 = q[0], v1 = q[1], v2 = q[2], v3 = q[3];
    d[0] = v0.x; d[1] = v0.y; d[2] = v1.x; d[3] = v1.y;
    d[4] = v2.x; d[5] = v2.y; d[6] = v3.x; d[7] = v3.y;
}
__device__ __forceinline__ float tanha(float x) {
    float r; asm("tanh.approx.f32 %0, %1;" : "=f"(r) : "f"(x)); return r;
}
__device__ __forceinline__ void cp16(u32 saddr, const float* g) {
    asm volatile("cp.async.cg.shared.global [%0], [%1], 16;" :: "r"(saddr), "l"(g));
}
__device__ __forceinline__ void cp_commit() { asm volatile("cp.async.commit_group;"); }
__device__ __forceinline__ void cp_wait0()  { asm volatile("cp.async.wait_group 0;"); }

// One LSTM layer. Warp = TWO batch elements (lanes 0-15 / 16-31).
// Lane (half, j) owns hidden unit j of its batch: gate rows j, 16+j, 32+j, 48+j.
// Weights in registers (f32x2; sigmoid rows pre-scaled by 0.5). h via smem.
// x staged via cp.async chunks; x-projection pipelined one step ahead.
// The warp is convergent through the step, so the STS->LDS h handoff needs no
// per-step __syncwarp (kept only at chunk boundaries for cp.async visibility).
template <bool WRITE_ALL>
__global__ void __launch_bounds__(224, 1)
lstm_layer(const float* __restrict__ in, float* __restrict__ out,
           const float* __restrict__ Wih, const float* __restrict__ Whh,
           const float* __restrict__ bih, const float* __restrict__ bhh)
{
    __shared__ __align__(16) float sh[WPB][2][2][Hn];            // [warp][parity][half][j]
    __shared__ __align__(16) float xs[WPB][2][2][CHUNK][Hn];     // [warp][buf][half][step][j]

    const int warp = threadIdx.x >> 5;
    const int lane = threadIdx.x & 31;
    const int half = lane >> 4;
    const int j    = lane & 15;
    const int b    = blockIdx.x * BPC + warp * 2 + half;
    if (b >= Bn) return;   // warp-uniform exit

    // ---- weights -> registers; sigmoid-gate rows scaled by 0.5 ----
    ull wx[4][8], wh[4][8], bias[4];
    const ull halfpack = pack2(0.5f, 0.5f);
#pragma unroll
    for (int q = 0; q < 4; q++) {
        const int row = q * Hn + j;          // q: 0=i 1=f 2=g 3=o
        load8(wx[q], Wih + row * Hn);
        load8(wh[q], Whh + row * Hn);
        float bb = bih[row] + bhh[row];
        if (q != 2) {
            bb *= 0.5f;
#pragma unroll
            for (int i = 0; i < 8; i++) {
                wx[q][i] = fmul2(wx[q][i], halfpack);
                wh[q][i] = fmul2(wh[q][i], halfpack);
            }
        }
        bias[q] = pack2(bb, 0.0f);
    }

    sh[warp][0][half][j] = 0.0f;
    float c = 0.0f;

    const float* xptr = in + (size_t)b * Tn * Hn;
    float*       orow = out + (size_t)b * Tn * Hn;

    // prefetch chunk 0 into buf 0 and wait
    {
        u32 s0 = (u32)__cvta_generic_to_shared(&xs[warp][0][half][0][0]);
#pragma unroll
        for (int k = 0; k < 4; k++)
            cp16(s0 + (k * 16 + j) * 16, xptr + (k * 16 + j) * 4);
        cp_commit();
        cp_wait0();
    }
    __syncwarp();

    // initial x-projection: chunk 0, step 0
    ull ax0, ax1, ax2, ax3;
    {
        ull xv[8];
        load8(xv, &xs[warp][0][half][0][0]);
        ax0 = bias[0]; ax1 = bias[1]; ax2 = bias[2]; ax3 = bias[3];
#pragma unroll
        for (int i = 0; i < 8; i++) {
            ffma2(ax0, wx[0][i], xv[i]); ffma2(ax1, wx[1][i], xv[i]);
            ffma2(ax2, wx[2][i], xv[i]); ffma2(ax3, wx[3][i], xv[i]);
        }
    }

    // One LSTM step: h-proj on pipelined ax, refill ax from xsrc, activations.
    auto STEP = [&](int s, int t, const float* xsrc) {
        ull hp[8];
        load8(hp, &sh[warp][s & 1][half][0]);
        ull a0 = ax0, a1 = ax1, a2 = ax2, a3 = ax3;
#pragma unroll
        for (int i = 0; i < 8; i++) {
            ffma2(a0, wh[0][i], hp[i]); ffma2(a1, wh[1][i], hp[i]);
            ffma2(a2, wh[2][i], hp[i]); ffma2(a3, wh[3][i], hp[i]);
        }
        // off-chain: next x-projection (fills the activation-latency window)
        {
            ull xv[8];
            load8(xv, xsrc);
            ax0 = bias[0]; ax1 = bias[1]; ax2 = bias[2]; ax3 = bias[3];
#pragma unroll
            for (int i = 0; i < 8; i++) {
                ffma2(ax0, wx[0][i], xv[i]); ffma2(ax1, wx[1][i], xv[i]);
                ffma2(ax2, wx[2][i], xv[i]); ffma2(ax3, wx[3][i], xv[i]);
            }
        }
        float2 F0 = u2f(a0), F1 = u2f(a1), F2 = u2f(a2), F3 = u2f(a3);
        const float vi = F0.x + F0.y;   // pre-halved
        const float vf = F1.x + F1.y;   // pre-halved
        const float vg = F2.x + F2.y;
        const float vo = F3.x + F3.y;   // pre-halved

        const float si = fmaf(0.5f, tanha(vi), 0.5f);
        const float sf = fmaf(0.5f, tanha(vf), 0.5f);
        const float tg = tanha(vg);
        const float so = fmaf(0.5f, tanha(vo), 0.5f);

        c = fmaf(sf, c, si * tg);
        const float h = so * tanha(c);

        // STS -> (next step's) LDS handoff: warp is convergent, program order
        // guarantees the store warp-instruction precedes the next load.
        sh[warp][(s + 1) & 1][half][j] = h;
        if (WRITE_ALL || t == Tn - 1)           // warp-uniform condition
            orow[t * Hn + j] = h;
    };

    for (int ch = 0; ch < NCHUNK; ch++) {
        const int cur = ch & 1;
        const int t0  = ch * CHUNK;

        // issue prefetch of chunk ch+1 into buf cur^1 (clamped refetch at tail)
        {
            const int nch = (ch + 1 < NCHUNK) ? ch + 1 : ch;
            const float* g = xptr + nch * (CHUNK * Hn);
            u32 s0 = (u32)__cvta_generic_to_shared(&xs[warp][cur ^ 1][half][0][0]);
#pragma unroll
            for (int k = 0; k < 4; k++)
                cp16(s0 + (k * 16 + j) * 16, g + (k * 16 + j) * 4);
            cp_commit();
        }

#pragma unroll 4
        for (int s = 0; s < 12; s++)
            STEP(s, t0 + s, &xs[warp][cur][half][s + 1][0]);

        cp_wait0();          // chunk ch+1 resident (issued 12 steps ago)
        __syncwarp();        // cross-lane visibility of cp.async fills

        STEP(12, t0 + 12, &xs[warp][cur][half][13][0]);
        STEP(13, t0 + 13, &xs[warp][cur][half][14][0]);
        STEP(14, t0 + 14, &xs[warp][cur][half][15][0]);
        // s=15: refill ax from the NEXT chunk's slot 0 (already resident)
        STEP(15, t0 + 15, &xs[warp][cur ^ 1][half][0][0]);
    }
}

// Readout: position = last @ Wp^T + bp ; orientation = tanh(last @ Wo^T + bo)
__global__ void head_kernel(const float* __restrict__ hbuf,
                            const float* __restrict__ Wp, const float* __restrict__ bp,
                            const float* __restrict__ Wo, const float* __restrict__ bo,
                            float* __restrict__ out)
{
    int b = blockIdx.x * blockDim.x + threadIdx.x;
    if (b >= Bn) return;
    const float* h = hbuf + (size_t)b * Tn * Hn + (size_t)(Tn - 1) * Hn;
    float hv[16];
#pragma unroll
    for (int i = 0; i < 16; i++) hv[i] = h[i];

#pragma unroll
    for (int r = 0; r < 3; r++) {
        float s = bp[r];
#pragma unroll
        for (int k = 0; k < 16; k++) s += hv[k] * Wp[r * 16 + k];
        out[b * 6 + r] = s;
    }
#pragma unroll
    for (int r = 0; r < 3; r++) {
        float s = bo[r];
#pragma unroll
        for (int k = 0; k < 16; k++) s += hv[k] * Wo[r * 16 + k];
        out[b * 6 + 3 + r] = tanha(s);
    }
}

extern "C" void kernel_launch(void* const* d_in, const int* in_sizes, int n_in,
                              void* d_out, int out_size)
{
    const float* x   = (const float*)d_in[0];
    const float* Wih = (const float*)d_in[1];
    const float* Whh = (const float*)d_in[2];
    const float* bih = (const float*)d_in[3];
    const float* bhh = (const float*)d_in[4];
    const float* Wp  = (const float*)d_in[5];
    const float* bp  = (const float*)d_in[6];
    const float* Wo  = (const float*)d_in[7];
    const float* bo  = (const float*)d_in[8];
    float* out = (float*)d_out;

    float *bufA, *bufB;
    cudaGetSymbolAddress((void**)&bufA, g_bufA);
    cudaGetSymbolAddress((void**)&bufB, g_bufB);

    const float* cur = x;
    for (int l = 0; l < Ln; l++) {
        float* o = (l & 1) ? bufB : bufA;
        if (l != Ln - 1)
            lstm_layer<true><<<NBLK, 224>>>(cur, o,
                                            Wih + (size_t)l * 64 * Hn,
                                            Whh + (size_t)l * 64 * Hn,
                                            bih + (size_t)l * 64,
                                            bhh + (size_t)l * 64);
        else
            lstm_layer<false><<<NBLK, 224>>>(cur, o,
                                             Wih + (size_t)l * 64 * Hn,
                                             Whh + (size_t)l * 64 * Hn,
                                             bih + (size_t)l * 64,
                                             bhh + (size_t)l * 64);
        cur = o;
    }
    head_kernel<<<(Bn + 255) / 256, 256>>>(cur, Wp, bp, Wo, bo, out);
}